// round 4
// baseline (speedup 1.0000x reference)
#include <cuda_runtime.h>
#include <cuda_bf16.h>

// loss = sum_{b,c,s,h,w} (out[b,c,2s,h,w] - target[b,c,2s+1,h,w])^2 / (C*H*Wd * W/2)
// B=8, C=32, W=16 (s=0..7), H=128, Wd=128.
//
// 2048 slabs (g = flattened b,c,s). Slab g:
//   out float4 base : out4 + (g<<13)          (4096 float4 = 64 KB)
//   tgt float4 base : tgt4 + (g<<13) + 4096   (4096 float4 = 64 KB)
// Kernel A: one CTA per slab, 256 threads x 16 float4 pairs, no fence/atomic tail.
// Kernel B: one 1024-thread CTA sums the 2048 partials in double and scales.

#define NBLOCKS 2048
#define NTHREADS 256
#define PER_THREAD 16       // 4096 / 256
#define FIN_THREADS 1024

__device__ float g_partials[NBLOCKS];

__global__ __launch_bounds__(NTHREADS) void cont_loss_partial_kernel(
    const float4* __restrict__ out4, const float4* __restrict__ tgt4)
{
    const long long base = ((long long)blockIdx.x << 13);
    const float4* __restrict__ op = out4 + base + threadIdx.x;
    const float4* __restrict__ tp = tgt4 + base + 4096 + threadIdx.x;

    float a0 = 0.0f, a1 = 0.0f, a2 = 0.0f, a3 = 0.0f;
    #pragma unroll
    for (int k = 0; k < PER_THREAD; k++) {
        float4 o = op[k * NTHREADS];
        float4 t = tp[k * NTHREADS];
        float d0 = o.x - t.x;
        float d1 = o.y - t.y;
        float d2 = o.z - t.z;
        float d3 = o.w - t.w;
        a0 = fmaf(d0, d0, a0);
        a1 = fmaf(d1, d1, a1);
        a2 = fmaf(d2, d2, a2);
        a3 = fmaf(d3, d3, a3);
    }
    float acc = (a0 + a1) + (a2 + a3);

    // deterministic block reduction
    __shared__ float sbuf[NTHREADS];
    sbuf[threadIdx.x] = acc;
    __syncthreads();
    #pragma unroll
    for (int ofs = NTHREADS / 2; ofs > 0; ofs >>= 1) {
        if (threadIdx.x < ofs) sbuf[threadIdx.x] += sbuf[threadIdx.x + ofs];
        __syncthreads();
    }
    if (threadIdx.x == 0) g_partials[blockIdx.x] = sbuf[0];
}

__global__ __launch_bounds__(FIN_THREADS) void cont_loss_final_kernel(float* __restrict__ out)
{
    __shared__ double dbuf[FIN_THREADS];
    // each thread: 2 partials (both issued before use -> overlapped latency)
    double a = (double)g_partials[threadIdx.x];
    double b = (double)g_partials[threadIdx.x + FIN_THREADS];
    dbuf[threadIdx.x] = a + b;
    __syncthreads();
    #pragma unroll
    for (int ofs = FIN_THREADS / 2; ofs > 0; ofs >>= 1) {
        if (threadIdx.x < ofs) dbuf[threadIdx.x] += dbuf[threadIdx.x + ofs];
        __syncthreads();
    }
    if (threadIdx.x == 0) {
        const double scale = 1.0 / (524288.0 * 8.0);  // mean(C,H,Wd) then /half_win
        out[0] = (float)(dbuf[0] * scale);
    }
}

extern "C" void kernel_launch(void* const* d_in, const int* in_sizes, int n_in,
                              void* d_out, int out_size)
{
    const float4* out4 = (const float4*)d_in[0];
    const float4* tgt4 = (const float4*)d_in[1];
    float* o = (float*)d_out;

    cont_loss_partial_kernel<<<NBLOCKS, NTHREADS>>>(out4, tgt4);
    cont_loss_final_kernel<<<1, FIN_THREADS>>>(o);
}

// round 5
// speedup vs baseline: 1.0449x; 1.0449x over previous
#include <cuda_runtime.h>
#include <cuda_bf16.h>

// loss = sum_{b,c,s,h,w} (out[b,c,2s,h,w] - target[b,c,2s+1,h,w])^2 / (C*H*Wd * W/2)
// B=8, C=32, W=16 (s=0..7), H=128, Wd=128.
//
// 2048 slabs (g = flattened b,c,s). Slab g:
//   out float4 base : out4 + (g<<13)          (4096 float4 = 64 KB)
//   tgt float4 base : tgt4 + (g<<13) + 4096   (4096 float4 = 64 KB)
// One CTA per slab. Fused last-block-done reduction using an acq_rel atomic
// (no __threadfence -> no CCTL.IVALL L1 flush per CTA).

#define NBLOCKS 2048
#define NTHREADS 256
#define PER_THREAD 16   // 4096 / 256

__device__ float g_partials[NBLOCKS];
__device__ unsigned int g_count = 0;   // re-armed by last block -> graph-replay safe

__global__ __launch_bounds__(NTHREADS) void cont_loss_fused_kernel(
    const float4* __restrict__ out4, const float4* __restrict__ tgt4,
    float* __restrict__ result)
{
    const long long base = ((long long)blockIdx.x << 13);
    const float4* __restrict__ op = out4 + base + threadIdx.x;
    const float4* __restrict__ tp = tgt4 + base + 4096 + threadIdx.x;

    float a0 = 0.0f, a1 = 0.0f, a2 = 0.0f, a3 = 0.0f;
    #pragma unroll
    for (int k = 0; k < PER_THREAD; k++) {
        float4 o = op[k * NTHREADS];
        float4 t = tp[k * NTHREADS];
        float d0 = o.x - t.x;
        float d1 = o.y - t.y;
        float d2 = o.z - t.z;
        float d3 = o.w - t.w;
        a0 = fmaf(d0, d0, a0);
        a1 = fmaf(d1, d1, a1);
        a2 = fmaf(d2, d2, a2);
        a3 = fmaf(d3, d3, a3);
    }
    float acc = (a0 + a1) + (a2 + a3);

    // warp shuffle reduction (deterministic tree)
    #pragma unroll
    for (int ofs = 16; ofs > 0; ofs >>= 1)
        acc += __shfl_down_sync(0xFFFFFFFFu, acc, ofs);

    __shared__ float swarp[NTHREADS / 32];
    const int lane = threadIdx.x & 31;
    const int wid  = threadIdx.x >> 5;
    if (lane == 0) swarp[wid] = acc;
    __syncthreads();

    __shared__ bool s_is_last;
    if (threadIdx.x == 0) {
        float blk = 0.0f;
        #pragma unroll
        for (int w = 0; w < NTHREADS / 32; w++) blk += swarp[w];
        __stcg(&g_partials[blockIdx.x], blk);          // L2-visible store
        unsigned int prev;
        // acq_rel atomic: release orders the partial store; acquire orders
        // the last block's subsequent loads. No membar/CCTL.IVALL emitted.
        asm volatile("atom.add.acq_rel.gpu.u32 %0, [%1], %2;"
                     : "=r"(prev) : "l"(&g_count), "r"(1u) : "memory");
        s_is_last = (prev == (unsigned int)(NBLOCKS - 1));
    }
    __syncthreads();

    if (s_is_last) {
        // Last CTA: sum all 2048 partials (L2-resident) in double, scale, write.
        double dacc = 0.0;
        #pragma unroll
        for (int k = 0; k < NBLOCKS / NTHREADS; k++)
            dacc += (double)__ldcg(&g_partials[threadIdx.x + k * NTHREADS]);

        #pragma unroll
        for (int ofs = 16; ofs > 0; ofs >>= 1)
            dacc += __shfl_down_sync(0xFFFFFFFFu, dacc, ofs);

        __shared__ double dwarp[NTHREADS / 32];
        if (lane == 0) dwarp[wid] = dacc;
        __syncthreads();
        if (threadIdx.x == 0) {
            double total = 0.0;
            #pragma unroll
            for (int w = 0; w < NTHREADS / 32; w++) total += dwarp[w];
            const double scale = 1.0 / (524288.0 * 8.0);  // mean(C,H,Wd), /half_win
            result[0] = (float)(total * scale);
            g_count = 0;  // re-arm for next graph replay
        }
    }
}

extern "C" void kernel_launch(void* const* d_in, const int* in_sizes, int n_in,
                              void* d_out, int out_size)
{
    const float4* out4 = (const float4*)d_in[0];
    const float4* tgt4 = (const float4*)d_in[1];
    float* o = (float*)d_out;

    cont_loss_fused_kernel<<<NBLOCKS, NTHREADS>>>(out4, tgt4, o);
}

// round 6
// speedup vs baseline: 1.0877x; 1.0409x over previous
#include <cuda_runtime.h>
#include <cuda_bf16.h>

// loss = sum_{b,c,s,h,w} (out[b,c,2s,h,w] - target[b,c,2s+1,h,w])^2 / (C*H*Wd * W/2)
// B=8, C=32, W=16 (s=0..7), H=128, Wd=128.
//
// 2048 slabs (g = flattened b,c,s). Slab g:
//   out float4 base : out4 + (g<<13)          (4096 float4 = 64 KB)
//   tgt float4 base : tgt4 + (g<<13) + 4096   (4096 float4 = 64 KB)
//
// One CTA per slab. Tail is FIRE-AND-FORGET: returnless red.add of the block
// partial into g_accum + release red.add of a counter; CTAs retire with zero
// waiting. A single spinner thread (CTA 2047) polls the counter, writes the
// scaled result, and re-arms the globals for graph replay.

#define NBLOCKS 2048
#define NTHREADS 256
#define PER_THREAD 16   // 4096 / 256

__device__ float        g_accum = 0.0f;  // re-armed by spinner each launch
__device__ unsigned int g_count = 0;     // re-armed by spinner each launch

__global__ __launch_bounds__(NTHREADS) void cont_loss_fused_kernel(
    const float4* __restrict__ out4, const float4* __restrict__ tgt4,
    float* __restrict__ result)
{
    const long long base = ((long long)blockIdx.x << 13);
    const float4* __restrict__ op = out4 + base + threadIdx.x;
    const float4* __restrict__ tp = tgt4 + base + 4096 + threadIdx.x;

    float a0 = 0.0f, a1 = 0.0f, a2 = 0.0f, a3 = 0.0f;
    #pragma unroll
    for (int k = 0; k < PER_THREAD; k++) {
        float4 o = op[k * NTHREADS];
        float4 t = tp[k * NTHREADS];
        float d0 = o.x - t.x;
        float d1 = o.y - t.y;
        float d2 = o.z - t.z;
        float d3 = o.w - t.w;
        a0 = fmaf(d0, d0, a0);
        a1 = fmaf(d1, d1, a1);
        a2 = fmaf(d2, d2, a2);
        a3 = fmaf(d3, d3, a3);
    }
    float acc = (a0 + a1) + (a2 + a3);

    // warp shuffle reduction (deterministic within-block tree)
    #pragma unroll
    for (int ofs = 16; ofs > 0; ofs >>= 1)
        acc += __shfl_down_sync(0xFFFFFFFFu, acc, ofs);

    __shared__ float swarp[NTHREADS / 32];
    const int lane = threadIdx.x & 31;
    const int wid  = threadIdx.x >> 5;
    if (lane == 0) swarp[wid] = acc;
    __syncthreads();

    if (threadIdx.x == 0) {
        float blk = 0.0f;
        #pragma unroll
        for (int w = 0; w < NTHREADS / 32; w++) blk += swarp[w];

        // Fire-and-forget: no returns, no waits. Release on the counter bump
        // orders the g_accum add before it.
        asm volatile("red.add.relaxed.gpu.f32 [%0], %1;"
                     :: "l"(&g_accum), "f"(blk) : "memory");
        asm volatile("red.add.release.gpu.u32 [%0], %1;"
                     :: "l"(&g_count), "r"(1u) : "memory");

        // Single spinner thread finalizes once every CTA has arrived.
        if (blockIdx.x == NBLOCKS - 1) {
            unsigned int c;
            do {
                __nanosleep(200);
                asm volatile("ld.acquire.gpu.u32 %0, [%1];"
                             : "=r"(c) : "l"(&g_count));
            } while (c < (unsigned int)NBLOCKS);

            float total;
            asm volatile("ld.acquire.gpu.f32 %0, [%1];"
                         : "=f"(total) : "l"(&g_accum));
            const double scale = 1.0 / (524288.0 * 8.0);  // mean(C,H,Wd), /half_win
            result[0] = (float)((double)total * scale);

            // re-arm for next graph replay (everyone else is done)
            asm volatile("st.relaxed.gpu.f32 [%0], %1;"
                         :: "l"(&g_accum), "f"(0.0f) : "memory");
            asm volatile("st.relaxed.gpu.u32 [%0], %1;"
                         :: "l"(&g_count), "r"(0u) : "memory");
        }
    }
    // all other threads fall through and retire immediately
}

extern "C" void kernel_launch(void* const* d_in, const int* in_sizes, int n_in,
                              void* d_out, int out_size)
{
    const float4* out4 = (const float4*)d_in[0];
    const float4* tgt4 = (const float4*)d_in[1];
    float* o = (float*)d_out;

    cont_loss_fused_kernel<<<NBLOCKS, NTHREADS>>>(out4, tgt4, o);
}